// round 7
// baseline (speedup 1.0000x reference)
#include <cuda_runtime.h>
#include <cstdint>

#define B_SZ  32
#define T_LEN 2048
#define I_DIM 128
#define H_DIM 256

// Scratch (allocation-free rule: __device__ globals)
__device__ __align__(256) float g_xB[B_SZ * T_LEN * H_DIM];  // 67 MB
__device__ __align__(256) float g_hs[B_SZ * T_LEN * H_DIM];  // 67 MB

// ---------------------------------------------------------------------------
// helpers
// ---------------------------------------------------------------------------
__device__ __forceinline__ uint32_t smem_u32(const void* p) {
    uint32_t a;
    asm("{ .reg .u64 t; cvta.to.shared.u64 t, %1; cvt.u32.u64 %0, t; }"
        : "=r"(a) : "l"(p));
    return a;
}

// packed fp32x2 FMA: full-rate FMA path on sm_103a (3-reg FFMA is half rate)
__device__ __forceinline__ void ffma2(unsigned long long& acc,
                                      unsigned long long a,
                                      unsigned long long b) {
    asm("fma.rn.f32x2 %0, %1, %2, %0;" : "+l"(acc) : "l"(a), "l"(b));
}
__device__ __forceinline__ unsigned long long pack2(float lo, float hi) {
    unsigned long long r;
    asm("mov.b64 %0, {%1, %2};" : "=l"(r) : "f"(lo), "f"(hi));
    return r;
}
__device__ __forceinline__ float2 unpack2(unsigned long long v) {
    float2 r;
    asm("mov.b64 {%0, %1}, %2;" : "=f"(r.x), "=f"(r.y) : "l"(v));
    return r;
}

// ---------------------------------------------------------------------------
// Scan kernel: cluster of 2 CTAs per batch element.
//   CTA rank r owns output columns j in [128r, 128r+128).
//   256 threads: jj = tid&127 (output), q = tid>>7 (k-half: 128 k each).
//   A column slices live in registers as packed f32x2 (64 regs/thread).
//   Per step: FFMA2 dot, pair-reduce in smem, tanh, exchange 128 h values
//   with the peer CTA through DSMEM + mbarrier (release/acquire, cluster).
// ---------------------------------------------------------------------------
__global__ void __cluster_dims__(2, 1, 1) __launch_bounds__(256, 1)
scan_kernel(const float* __restrict__ A)
{
    __shared__ __align__(16) float h_s[2][H_DIM];   // double-buffered state
    __shared__ float scratch[128];                  // pair-reduce partials
    __shared__ __align__(8) unsigned long long mbar[1];

    const int tid   = threadIdx.x;
    const int jj    = tid & 127;
    const int q     = tid >> 7;            // 0 or 1 (k-half)
    uint32_t rank;
    asm("mov.u32 %0, %%cluster_ctarank;" : "=r"(rank));
    const int b     = blockIdx.x >> 1;
    const int j     = (int)rank * 128 + jj;   // global output column
    const int kbase = q * 128;

    // --- A slice -> registers, packed as (A[k][j], A[k+1][j]) pairs --------
    unsigned long long Ar[64];
#pragma unroll
    for (int m = 0; m < 64; m++) {
        float a0 = A[(size_t)(kbase + 2 * m)     * H_DIM + j];
        float a1 = A[(size_t)(kbase + 2 * m + 1) * H_DIM + j];
        Ar[m] = pack2(a0, a1);
    }

    // --- init shared state + mbarrier --------------------------------------
    h_s[0][tid] = 0.0f;          // tid covers 0..255 == H_DIM
    h_s[1][tid] = 0.0f;
    uint32_t mbar_a = smem_u32(mbar);
    if (tid == 0) {
        asm volatile("mbarrier.init.shared.b64 [%0], %1;"
                     :: "r"(mbar_a), "r"(128u) : "memory");
    }
    // cluster-wide visibility of init/zeros before any remote traffic
    asm volatile("barrier.cluster.arrive.aligned;" ::: "memory");
    asm volatile("barrier.cluster.wait.aligned;"   ::: "memory");

    // --- peer addresses (DSMEM) --------------------------------------------
    uint32_t peer = rank ^ 1u;
    uint32_t h0_a = smem_u32(&h_s[0][0]);
    uint32_t peer_h0, peer_mbar;
    asm("mapa.shared::cluster.u32 %0, %1, %2;" : "=r"(peer_h0)   : "r"(h0_a),   "r"(peer));
    asm("mapa.shared::cluster.u32 %0, %1, %2;" : "=r"(peer_mbar) : "r"(mbar_a), "r"(peer));

    // --- xB prefetch pipeline (distance 2 hides ~577cyc DRAM latency) ------
    const float* xb_base = g_xB + ((size_t)b * T_LEN) * H_DIM + j;
    float*       hs_out  = g_hs + ((size_t)b * T_LEN) * H_DIM + j;
    float xb_pre[2] = {0.0f, 0.0f};
    if (q == 0) {
        xb_pre[0] = __ldg(xb_base);
        xb_pre[1] = __ldg(xb_base + H_DIM);
    }

    // --- main scan loop -----------------------------------------------------
    for (int t = 0; t < T_LEN; t++) {
        const int cur = t & 1;

        // dot over my 128 k values (smem h is broadcast-read, A in regs)
        const ulonglong2* h2 =
            reinterpret_cast<const ulonglong2*>(&h_s[cur][kbase]);
        unsigned long long acc0 = 0ull, acc1 = 0ull;
#pragma unroll
        for (int m = 0; m < 32; m++) {
            ulonglong2 hv = h2[m];           // LDS.128: two packed f32x2
            ffma2(acc0, hv.x, Ar[2 * m]);
            ffma2(acc1, hv.y, Ar[2 * m + 1]);
        }
        float2 u0 = unpack2(acc0), u1 = unpack2(acc1);
        float partial = (u0.x + u0.y) + (u1.x + u1.y);

        if (q == 1) scratch[jj] = partial;
        __syncthreads();

        if (q == 0) {
            float tot = partial + scratch[jj] + xb_pre[t & 1];
            if (t + 2 < T_LEN)   // refill prefetch slot
                xb_pre[t & 1] = __ldg(xb_base + (size_t)(t + 2) * H_DIM);
            float hv = tanhf(tot);

            h_s[cur ^ 1][j] = hv;                        // local copy
            uint32_t ra = peer_h0 +
                          (uint32_t)(((cur ^ 1) * H_DIM + j) * 4);
            asm volatile("st.shared::cluster.f32 [%0], %1;"
                         :: "r"(ra), "f"(hv) : "memory"); // peer copy
            hs_out[(size_t)t * H_DIM] = hv;               // for out-GEMM

            // release: order my remote store before the peer's wait
            asm volatile(
                "mbarrier.arrive.release.cluster.shared::cluster.b64 _, [%0];"
                :: "r"(peer_mbar) : "memory");
        }
        __syncthreads();   // local h_s[next] visible CTA-wide

        // wait for the peer's 128 arrivals for this step (acquire, cluster)
        {
            uint32_t par = (uint32_t)(t & 1);
            asm volatile(
                "{\n\t.reg .pred P;\n"
                "W%=:\n\t"
                "mbarrier.try_wait.parity.acquire.cluster.shared::cta.b64 P, [%0], %1, 0x989680;\n\t"
                "@!P bra W%=;\n\t"
                "}"
                :: "r"(mbar_a), "r"(par) : "memory");
        }
    }

    asm volatile("barrier.cluster.arrive.aligned;" ::: "memory");
    asm volatile("barrier.cluster.wait.aligned;"   ::: "memory");
}

// ---------------------------------------------------------------------------
// fp32 tiled GEMM: C[M,N] = A[M,K] @ B[K,N], all row-major.
// 128x128 block tile, k-tile 16, 256 threads, 8x8 microtile.
// Accumulators are packed f32x2 (fma.rn.f32x2) -> full-rate FMA pipe.
// Assumes M%128==0, N%128==0, K%16==0 (holds for all three uses).
// ---------------------------------------------------------------------------
__global__ void __launch_bounds__(256)
gemm_f32(const float* __restrict__ Ag, const float* __restrict__ Bg,
         float* __restrict__ Cg, int M, int N, int K)
{
    __shared__ __align__(16) float As[16][128];   // transposed A tile
    __shared__ __align__(16) float Bs[16][128];

    const int tid = threadIdx.x;
    const int bm  = blockIdx.x * 128;
    const int bn  = blockIdx.y * 128;
    const int tx  = tid & 15;     // n direction
    const int ty  = tid >> 4;     // m direction
    const int m0  = ty * 8;
    const int n0  = tx * 8;

    unsigned long long acc[8][4];
#pragma unroll
    for (int i = 0; i < 8; i++)
#pragma unroll
        for (int p = 0; p < 4; p++) acc[i][p] = 0ull;

    for (int k0 = 0; k0 < K; k0 += 16) {
        // load A tile (128 rows x 16 cols), store transposed
#pragma unroll
        for (int l = 0; l < 2; l++) {
            int v  = tid + l * 256;
            int r  = v >> 2;
            int c4 = v & 3;
            float4 a = *reinterpret_cast<const float4*>(
                &Ag[(size_t)(bm + r) * K + k0 + c4 * 4]);
            As[c4 * 4 + 0][r] = a.x;
            As[c4 * 4 + 1][r] = a.y;
            As[c4 * 4 + 2][r] = a.z;
            As[c4 * 4 + 3][r] = a.w;
        }
        // load B tile (16 rows x 128 cols)
#pragma unroll
        for (int l = 0; l < 2; l++) {
            int v  = tid + l * 256;
            int kk = v >> 5;
            int c4 = v & 31;
            *reinterpret_cast<float4*>(&Bs[kk][c4 * 4]) =
                *reinterpret_cast<const float4*>(
                    &Bg[(size_t)(k0 + kk) * N + bn + c4 * 4]);
        }
        __syncthreads();

#pragma unroll
        for (int kk = 0; kk < 16; kk++) {
            float4 a0 = *reinterpret_cast<const float4*>(&As[kk][m0]);
            float4 a1 = *reinterpret_cast<const float4*>(&As[kk][m0 + 4]);
            ulonglong2 b0 = *reinterpret_cast<const ulonglong2*>(&Bs[kk][n0]);
            ulonglong2 b1 = *reinterpret_cast<const ulonglong2*>(&Bs[kk][n0 + 4]);

            unsigned long long ap[8];
            ap[0] = pack2(a0.x, a0.x); ap[1] = pack2(a0.y, a0.y);
            ap[2] = pack2(a0.z, a0.z); ap[3] = pack2(a0.w, a0.w);
            ap[4] = pack2(a1.x, a1.x); ap[5] = pack2(a1.y, a1.y);
            ap[6] = pack2(a1.z, a1.z); ap[7] = pack2(a1.w, a1.w);
            unsigned long long bv0 = b0.x, bv1 = b0.y, bv2 = b1.x, bv3 = b1.y;

#pragma unroll
            for (int i = 0; i < 8; i++) {
                ffma2(acc[i][0], ap[i], bv0);
                ffma2(acc[i][1], ap[i], bv1);
                ffma2(acc[i][2], ap[i], bv2);
                ffma2(acc[i][3], ap[i], bv3);
            }
        }
        __syncthreads();
    }

    // epilogue
#pragma unroll
    for (int i = 0; i < 8; i++) {
        float o[8];
#pragma unroll
        for (int p = 0; p < 4; p++) {
            float2 u = unpack2(acc[i][p]);
            o[2 * p] = u.x; o[2 * p + 1] = u.y;
        }
        float4* dst = reinterpret_cast<float4*>(
            &Cg[(size_t)(bm + m0 + i) * N + bn + n0]);
        dst[0] = make_float4(o[0], o[1], o[2], o[3]);
        dst[1] = make_float4(o[4], o[5], o[6], o[7]);
    }
}

// ---------------------------------------------------------------------------
// launch
// ---------------------------------------------------------------------------
extern "C" void kernel_launch(void* const* d_in, const int* in_sizes, int n_in,
                              void* d_out, int out_size)
{
    (void)in_sizes; (void)n_in; (void)out_size;
    const float* x  = (const float*)d_in[0];   // [32, 2048, 128]
    const float* A  = (const float*)d_in[1];   // [256, 256]
    const float* Bm = (const float*)d_in[2];   // [128, 256]
    const float* C  = (const float*)d_in[3];   // [256, 256]
    float* out = (float*)d_out;                // [32, 2048, 256]

    float* xB = nullptr;
    float* hs = nullptr;
    cudaGetSymbolAddress((void**)&xB, g_xB);   // pure query: capture-safe
    cudaGetSymbolAddress((void**)&hs, g_hs);

    const int M = B_SZ * T_LEN;                // 65536

    // 1) xB = x @ Bm   (M x 128) @ (128 x 256)
    gemm_f32<<<dim3(M / 128, H_DIM / 128), 256>>>(x, Bm, xB, M, H_DIM, I_DIM);
    // 2) sequential tanh scan, 32 clusters of 2 CTAs
    scan_kernel<<<B_SZ * 2, 256>>>(A);
    // 3) out = hs @ C  (M x 256) @ (256 x 256)
    gemm_f32<<<dim3(M / 128, H_DIM / 128), 256>>>(hs, C, out, M, H_DIM, H_DIM);
}